// round 2
// baseline (speedup 1.0000x reference)
#include <cuda_runtime.h>

// Problem constants (match reference)
#define NN 50000
#define EE 400000
#define INDIM 256
#define HDIM 128      // HEADS * OUT_DIM
#define ALPHA_C 0.2f
#define INV_TEMP (1.0f / 0.55f)

// Scratch (device globals; allocation-free per harness rules)
__device__ float g_Wh[NN * HDIM];       // [n][h*64+f]
__device__ float g_U[NN * HDIM];        // [n][h*64+c]  (src-side attn features)
__device__ float g_V[NN * HDIM];        // [n][h*64+c]  (dst-side attn features)
__device__ float g_logits[EE * 2];      // [e][h]
__device__ int   g_rowptr[NN + 1];

// ---------------------------------------------------------------------------
// K0: CSR row pointers from sorted dst. rowptr[n] = first edge with dst >= n.
// ---------------------------------------------------------------------------
__global__ void k_rowptr(const int* __restrict__ dst, int E, int N) {
    int e = blockIdx.x * blockDim.x + threadIdx.x;
    if (e > E) return;
    int cur  = (e < E) ? dst[e] : N;
    int prev = (e == 0) ? -1 : dst[e - 1];
    for (int n = prev + 1; n <= cur; n++) g_rowptr[n] = e;
}

// ---------------------------------------------------------------------------
// K1: Wh = x @ W   [N,256] x [256,128] -> [N,128]   (W is [256][2][64] = [256][128])
// 128x128 block tile, BK=16, 256 threads, 8x8 microtile. smem = 16.25 KB.
// ---------------------------------------------------------------------------
__global__ __launch_bounds__(256) void k_gemm_wh(const float* __restrict__ x,
                                                 const float* __restrict__ W, int N) {
    __shared__ float As[16][128];   // k-major
    __shared__ float Bs[16][132];   // k-major, padded
    int tid = threadIdx.x;
    int bm = blockIdx.x * 128;
    int tx = tid & 15, ty = tid >> 4;

    float acc[8][8];
#pragma unroll
    for (int i = 0; i < 8; i++)
#pragma unroll
        for (int j = 0; j < 8; j++) acc[i][j] = 0.f;

    for (int k0 = 0; k0 < INDIM; k0 += 16) {
        // A tile: 128 rows x 16 k  (512 float4 chunks; 2/thread)
#pragma unroll
        for (int i = 0; i < 2; i++) {
            int chunk = tid * 2 + i;
            int row = chunk >> 2;
            int kp = (chunk & 3) * 4;
            float4 v = make_float4(0.f, 0.f, 0.f, 0.f);
            int grow = bm + row;
            if (grow < N) v = *(const float4*)(x + (size_t)grow * INDIM + k0 + kp);
            As[kp + 0][row] = v.x;
            As[kp + 1][row] = v.y;
            As[kp + 2][row] = v.z;
            As[kp + 3][row] = v.w;
        }
        // B tile: 16 k x 128 cols (already k-major in gmem)
#pragma unroll
        for (int i = 0; i < 2; i++) {
            int chunk = tid + i * 256;
            int kk = chunk >> 5;
            int col = (chunk & 31) * 4;
            *(float4*)&Bs[kk][col] = *(const float4*)(W + (size_t)(k0 + kk) * HDIM + col);
        }
        __syncthreads();
#pragma unroll
        for (int kk = 0; kk < 16; kk++) {
            float a[8], b[8];
            *(float4*)&a[0] = *(const float4*)&As[kk][ty * 8];
            *(float4*)&a[4] = *(const float4*)&As[kk][ty * 8 + 4];
            *(float4*)&b[0] = *(const float4*)&Bs[kk][tx * 8];
            *(float4*)&b[4] = *(const float4*)&Bs[kk][tx * 8 + 4];
#pragma unroll
            for (int i = 0; i < 8; i++)
#pragma unroll
                for (int j = 0; j < 8; j++)
                    acc[i][j] = fmaf(a[i], b[j], acc[i][j]);
        }
        __syncthreads();
    }
#pragma unroll
    for (int i = 0; i < 8; i++) {
        int grow = bm + ty * 8 + i;
        if (grow < N) {
            float4 s0 = make_float4(acc[i][0], acc[i][1], acc[i][2], acc[i][3]);
            float4 s1 = make_float4(acc[i][4], acc[i][5], acc[i][6], acc[i][7]);
            *(float4*)(g_Wh + (size_t)grow * HDIM + tx * 8)     = s0;
            *(float4*)(g_Wh + (size_t)grow * HDIM + tx * 8 + 4) = s1;
        }
    }
}

// ---------------------------------------------------------------------------
// K2: U/V = Wh_h @ Wa_{src/dst,h}   4 sub-GEMMs [N,64]x[64,64] (blockIdx.y = combo)
// GATv2 decomposition: leaky_relu comes after the src+dst sum, so the edge
// matmul factors into per-node projections.
// W_attn layout: [h][2*64][64]; rows 0..63 multiply Wh_src, 64..127 multiply Wh_dst.
// A tile stored k-major (transposed): As_t[kk][row]. smem = 32KB + 16KB = 48KB.
// ---------------------------------------------------------------------------
__global__ __launch_bounds__(256) void k_gemm_uv(const float* __restrict__ Wattn, int N) {
    int h = blockIdx.y & 1;
    int p = blockIdx.y >> 1;               // 0 -> U (src part), 1 -> V (dst part)
    __shared__ float As_t[64][128];        // [k][row]
    __shared__ float Bs[64][64];           // [k][col]
    int tid = threadIdx.x;
    int bm = blockIdx.x * 128;

    const float* Bsrc = Wattn + h * (128 * 64) + p * (64 * 64);
#pragma unroll
    for (int i = 0; i < 4; i++) {          // 64x64 = 1024 float4 chunks
        int c = tid + i * 256;
        int f = c >> 4, cc = (c & 15) * 4;
        *(float4*)&Bs[f][cc] = *(const float4*)(Bsrc + f * 64 + cc);
    }
#pragma unroll
    for (int i = 0; i < 8; i++) {          // A tile 128 rows x 64 k = 2048 float4 chunks
        int c = tid + i * 256;
        int row = c >> 4, kp = (c & 15) * 4;
        int grow = bm + row;
        float4 v = make_float4(0.f, 0.f, 0.f, 0.f);
        if (grow < N) v = *(const float4*)(g_Wh + (size_t)grow * HDIM + h * 64 + kp);
        As_t[kp + 0][row] = v.x;
        As_t[kp + 1][row] = v.y;
        As_t[kp + 2][row] = v.z;
        As_t[kp + 3][row] = v.w;
    }
    __syncthreads();

    int tx = tid & 7, ty = tid >> 3;       // 8 col-groups x 32 row-groups; 4 rows x 8 cols each
    float acc[4][8];
#pragma unroll
    for (int r = 0; r < 4; r++)
#pragma unroll
        for (int j = 0; j < 8; j++) acc[r][j] = 0.f;

#pragma unroll 8
    for (int kk = 0; kk < 64; kk++) {
        float b[8];
        *(float4*)&b[0] = *(const float4*)&Bs[kk][tx * 8];
        *(float4*)&b[4] = *(const float4*)&Bs[kk][tx * 8 + 4];
        float a0 = As_t[kk][ty * 4 + 0];
        float a1 = As_t[kk][ty * 4 + 1];
        float a2 = As_t[kk][ty * 4 + 2];
        float a3 = As_t[kk][ty * 4 + 3];
#pragma unroll
        for (int j = 0; j < 8; j++) {
            acc[0][j] = fmaf(a0, b[j], acc[0][j]);
            acc[1][j] = fmaf(a1, b[j], acc[1][j]);
            acc[2][j] = fmaf(a2, b[j], acc[2][j]);
            acc[3][j] = fmaf(a3, b[j], acc[3][j]);
        }
    }

    float* Out = p ? g_V : g_U;
#pragma unroll
    for (int r = 0; r < 4; r++) {
        int grow = bm + ty * 4 + r;
        if (grow < N) {
            float4 s0 = make_float4(acc[r][0], acc[r][1], acc[r][2], acc[r][3]);
            float4 s1 = make_float4(acc[r][4], acc[r][5], acc[r][6], acc[r][7]);
            *(float4*)(Out + (size_t)grow * HDIM + h * 64 + tx * 8)     = s0;
            *(float4*)(Out + (size_t)grow * HDIM + h * 64 + tx * 8 + 4) = s1;
        }
    }
}

// ---------------------------------------------------------------------------
// K3: edge logits. One warp per edge; lane loads float4 of U[src]+V[dst]
// (lanes 0-15 = head0 channels, 16-31 = head1). Half-warp reduce.
// ---------------------------------------------------------------------------
__global__ __launch_bounds__(256) void k_logits(const float* __restrict__ avec,
                                                const int* __restrict__ src,
                                                const int* __restrict__ dst, int E) {
    int t = blockIdx.x * blockDim.x + threadIdx.x;
    int e = t >> 5, lane = t & 31;
    if (e >= E) return;
    int s = src[e], d = dst[e];
    const float4* U4 = (const float4*)g_U;
    const float4* V4 = (const float4*)g_V;
    float4 u = U4[(size_t)s * 32 + lane];
    float4 v = V4[(size_t)d * 32 + lane];
    float4 a = ((const float4*)avec)[lane];   // a_vec is [2][64] = 32 float4
    float z, q;
    q = u.x + v.x; z  = fmaxf(q, ALPHA_C * q) * a.x;
    q = u.y + v.y; z += fmaxf(q, ALPHA_C * q) * a.y;
    q = u.z + v.z; z += fmaxf(q, ALPHA_C * q) * a.z;
    q = u.w + v.w; z += fmaxf(q, ALPHA_C * q) * a.w;
#pragma unroll
    for (int off = 8; off; off >>= 1)
        z += __shfl_xor_sync(0xffffffffu, z, off);
    if ((lane & 15) == 0)
        g_logits[e * 2 + (lane >> 4)] = z * INV_TEMP;
}

// ---------------------------------------------------------------------------
// K4: warp-per-node segment softmax + weighted aggregation (no atomics).
// Two passes: (1) max, (2) fused exp-sum + unnormalized accumulate; divide once.
// Each lane owns 4 output channels of one head; head halves combined by shuffle.
// ---------------------------------------------------------------------------
__global__ __launch_bounds__(256) void k_aggregate(const int* __restrict__ src,
                                                   float* __restrict__ out, int N) {
    int t = blockIdx.x * blockDim.x + threadIdx.x;
    int n = t >> 5, lane = t & 31;
    if (n >= N) return;
    int e0 = g_rowptr[n], e1 = g_rowptr[n + 1];
    int h = lane >> 4;
    float4 acc = make_float4(0.f, 0.f, 0.f, 0.f);
    if (e1 > e0) {
        float m = -1e30f;
        for (int e = e0; e < e1; e++)
            m = fmaxf(m, g_logits[2 * e + h]);
        float ssum = 0.f;
        const float4* Wh4 = (const float4*)g_Wh;
        for (int e = e0; e < e1; e++) {
            float w = __expf(g_logits[2 * e + h] - m);
            ssum += w;
            float4 v = Wh4[(size_t)src[e] * 32 + lane];
            acc.x = fmaf(w, v.x, acc.x);
            acc.y = fmaf(w, v.y, acc.y);
            acc.z = fmaf(w, v.z, acc.z);
            acc.w = fmaf(w, v.w, acc.w);
        }
        float inv = 1.0f / (ssum + 1e-9f);
        acc.x *= inv; acc.y *= inv; acc.z *= inv; acc.w *= inv;
    }
    // mean over heads: lane l<16 combines with lane l+16 (same channels, other head)
    float bx = __shfl_down_sync(0xffffffffu, acc.x, 16);
    float by = __shfl_down_sync(0xffffffffu, acc.y, 16);
    float bz = __shfl_down_sync(0xffffffffu, acc.z, 16);
    float bw = __shfl_down_sync(0xffffffffu, acc.w, 16);
    if (lane < 16) {
        float4 r = make_float4((acc.x + bx) * 0.5f, (acc.y + by) * 0.5f,
                               (acc.z + bz) * 0.5f, (acc.w + bw) * 0.5f);
        ((float4*)out)[(size_t)n * 16 + lane] = r;
    }
}

// ---------------------------------------------------------------------------
extern "C" void kernel_launch(void* const* d_in, const int* in_sizes, int n_in,
                              void* d_out, int out_size) {
    const float* x     = (const float*)d_in[0];
    const float* W     = (const float*)d_in[1];
    const float* Wattn = (const float*)d_in[2];
    const float* avec  = (const float*)d_in[3];
    const int*   src   = (const int*)d_in[4];
    const int*   dst   = (const int*)d_in[5];
    float* out = (float*)d_out;
    int N = in_sizes[0] / INDIM;
    int E = in_sizes[4];

    k_rowptr<<<(E + 1 + 255) / 256, 256>>>(dst, E, N);
    k_gemm_wh<<<(N + 127) / 128, 256>>>(x, W, N);
    k_gemm_uv<<<dim3((N + 127) / 128, 4), 256>>>(Wattn, N);
    k_logits<<<(E + 7) / 8, 256>>>(avec, src, dst, E);
    k_aggregate<<<(N + 7) / 8, 256>>>(src, out, N);
}

// round 4
// speedup vs baseline: 1.0566x; 1.0566x over previous
#include <cuda_runtime.h>

// Problem constants (match reference)
#define NN 50000
#define EE 400000
#define INDIM 256
#define HDIM 128      // HEADS * OUT_DIM
#define ALPHA_C 0.2f
#define INV_TEMP (1.0f / 0.55f)

// Scratch (device globals; allocation-free per harness rules)
__device__ float g_Wh[NN * HDIM];       // [n][h*64+f]
__device__ float g_U[NN * HDIM];        // [n][h*64+c]  (src-side attn features)
__device__ float g_V[NN * HDIM];        // [n][h*64+c]  (dst-side attn features)
__device__ float g_logits[EE * 2];      // overflow spill only (deg > 64)
__device__ int   g_rowptr[NN + 1];

// ---------------------------------------------------------------------------
// K0: CSR row pointers from sorted dst. rowptr[n] = first edge with dst >= n.
// ---------------------------------------------------------------------------
__global__ void k_rowptr(const int* __restrict__ dst, int E, int N) {
    int e = blockIdx.x * blockDim.x + threadIdx.x;
    if (e > E) return;
    int cur  = (e < E) ? dst[e] : N;
    int prev = (e == 0) ? -1 : dst[e - 1];
    for (int n = prev + 1; n <= cur; n++) g_rowptr[n] = e;
}

// ---------------------------------------------------------------------------
// K1: Wh = x @ W   [N,256] x [256,128] -> [N,128]
// 128x128 block tile, BK=16, 256 threads, 8x8 microtile. smem = 16.25 KB.
// ---------------------------------------------------------------------------
__global__ __launch_bounds__(256) void k_gemm_wh(const float* __restrict__ x,
                                                 const float* __restrict__ W, int N) {
    __shared__ float As[16][128];   // k-major
    __shared__ float Bs[16][132];   // k-major, padded
    int tid = threadIdx.x;
    int bm = blockIdx.x * 128;
    int tx = tid & 15, ty = tid >> 4;

    float acc[8][8];
#pragma unroll
    for (int i = 0; i < 8; i++)
#pragma unroll
        for (int j = 0; j < 8; j++) acc[i][j] = 0.f;

    for (int k0 = 0; k0 < INDIM; k0 += 16) {
#pragma unroll
        for (int i = 0; i < 2; i++) {
            int chunk = tid * 2 + i;
            int row = chunk >> 2;
            int kp = (chunk & 3) * 4;
            float4 v = make_float4(0.f, 0.f, 0.f, 0.f);
            int grow = bm + row;
            if (grow < N) v = *(const float4*)(x + (size_t)grow * INDIM + k0 + kp);
            As[kp + 0][row] = v.x;
            As[kp + 1][row] = v.y;
            As[kp + 2][row] = v.z;
            As[kp + 3][row] = v.w;
        }
#pragma unroll
        for (int i = 0; i < 2; i++) {
            int chunk = tid + i * 256;
            int kk = chunk >> 5;
            int col = (chunk & 31) * 4;
            *(float4*)&Bs[kk][col] = *(const float4*)(W + (size_t)(k0 + kk) * HDIM + col);
        }
        __syncthreads();
#pragma unroll
        for (int kk = 0; kk < 16; kk++) {
            float a[8], b[8];
            *(float4*)&a[0] = *(const float4*)&As[kk][ty * 8];
            *(float4*)&a[4] = *(const float4*)&As[kk][ty * 8 + 4];
            *(float4*)&b[0] = *(const float4*)&Bs[kk][tx * 8];
            *(float4*)&b[4] = *(const float4*)&Bs[kk][tx * 8 + 4];
#pragma unroll
            for (int i = 0; i < 8; i++)
#pragma unroll
                for (int j = 0; j < 8; j++)
                    acc[i][j] = fmaf(a[i], b[j], acc[i][j]);
        }
        __syncthreads();
    }
#pragma unroll
    for (int i = 0; i < 8; i++) {
        int grow = bm + ty * 8 + i;
        if (grow < N) {
            float4 s0 = make_float4(acc[i][0], acc[i][1], acc[i][2], acc[i][3]);
            float4 s1 = make_float4(acc[i][4], acc[i][5], acc[i][6], acc[i][7]);
            *(float4*)(g_Wh + (size_t)grow * HDIM + tx * 8)     = s0;
            *(float4*)(g_Wh + (size_t)grow * HDIM + tx * 8 + 4) = s1;
        }
    }
}

// ---------------------------------------------------------------------------
// K2: U/V = Wh_h @ Wa_{src/dst,h}   4 sub-GEMMs [N,64]x[64,64] (blockIdx.y)
// GATv2 decomposition: leaky_relu comes after the src+dst sum, so the edge
// matmul factors into per-node projections.
// ---------------------------------------------------------------------------
__global__ __launch_bounds__(256) void k_gemm_uv(const float* __restrict__ Wattn, int N) {
    int h = blockIdx.y & 1;
    int p = blockIdx.y >> 1;               // 0 -> U (src part), 1 -> V (dst part)
    __shared__ float As_t[64][128];        // [k][row]
    __shared__ float Bs[64][64];           // [k][col]
    int tid = threadIdx.x;
    int bm = blockIdx.x * 128;

    const float* Bsrc = Wattn + h * (128 * 64) + p * (64 * 64);
#pragma unroll
    for (int i = 0; i < 4; i++) {
        int c = tid + i * 256;
        int f = c >> 4, cc = (c & 15) * 4;
        *(float4*)&Bs[f][cc] = *(const float4*)(Bsrc + f * 64 + cc);
    }
#pragma unroll
    for (int i = 0; i < 8; i++) {
        int c = tid + i * 256;
        int row = c >> 4, kp = (c & 15) * 4;
        int grow = bm + row;
        float4 v = make_float4(0.f, 0.f, 0.f, 0.f);
        if (grow < N) v = *(const float4*)(g_Wh + (size_t)grow * HDIM + h * 64 + kp);
        As_t[kp + 0][row] = v.x;
        As_t[kp + 1][row] = v.y;
        As_t[kp + 2][row] = v.z;
        As_t[kp + 3][row] = v.w;
    }
    __syncthreads();

    int tx = tid & 7, ty = tid >> 3;
    float acc[4][8];
#pragma unroll
    for (int r = 0; r < 4; r++)
#pragma unroll
        for (int j = 0; j < 8; j++) acc[r][j] = 0.f;

#pragma unroll 8
    for (int kk = 0; kk < 64; kk++) {
        float b[8];
        *(float4*)&b[0] = *(const float4*)&Bs[kk][tx * 8];
        *(float4*)&b[4] = *(const float4*)&Bs[kk][tx * 8 + 4];
        float a0 = As_t[kk][ty * 4 + 0];
        float a1 = As_t[kk][ty * 4 + 1];
        float a2 = As_t[kk][ty * 4 + 2];
        float a3 = As_t[kk][ty * 4 + 3];
#pragma unroll
        for (int j = 0; j < 8; j++) {
            acc[0][j] = fmaf(a0, b[j], acc[0][j]);
            acc[1][j] = fmaf(a1, b[j], acc[1][j]);
            acc[2][j] = fmaf(a2, b[j], acc[2][j]);
            acc[3][j] = fmaf(a3, b[j], acc[3][j]);
        }
    }

    float* Out = p ? g_V : g_U;
#pragma unroll
    for (int r = 0; r < 4; r++) {
        int grow = bm + ty * 4 + r;
        if (grow < N) {
            float4 s0 = make_float4(acc[r][0], acc[r][1], acc[r][2], acc[r][3]);
            float4 s1 = make_float4(acc[r][4], acc[r][5], acc[r][6], acc[r][7]);
            *(float4*)(Out + (size_t)grow * HDIM + h * 64 + tx * 8)     = s0;
            *(float4*)(Out + (size_t)grow * HDIM + h * 64 + tx * 8 + 4) = s1;
        }
    }
}

// ---------------------------------------------------------------------------
// K3 (fused logits + softmax + aggregate): one warp per dst node.
// Lanes 0-15 own head0 channels (4 each), lanes 16-31 head1.
// Pass 1: gather U[src], logit = a . lrelu(U[src] + V[n]); track max; cache
//         logit in per-warp smem (gmem spill for deg > 64).
// Pass 2: w = exp(l - max); accumulate w and w * Wh[src]; normalize once.
// Both passes software-pipeline the per-edge row gather.
// ---------------------------------------------------------------------------
__global__ __launch_bounds__(256) void k_edge_fused(const float* __restrict__ avec,
                                                    const int* __restrict__ src,
                                                    float* __restrict__ out, int N) {
    __shared__ float lbuf[8][2][64];
    int t = blockIdx.x * blockDim.x + threadIdx.x;
    int n = t >> 5, lane = t & 31;
    if (n >= N) return;
    int wslot = threadIdx.x >> 5;
    int e0 = g_rowptr[n], e1 = g_rowptr[n + 1];
    int h = lane >> 4;
    const float4* U4  = (const float4*)g_U;
    const float4* V4  = (const float4*)g_V;
    const float4* Wh4 = (const float4*)g_Wh;
    float4 a = ((const float4*)avec)[lane];   // a_vec is [2][64] = 32 float4
    float4 acc = make_float4(0.f, 0.f, 0.f, 0.f);

    if (e1 > e0) {
        float4 v = V4[(size_t)n * 32 + lane];      // dst features: once per node
        float m = -1e30f;

        // ---- pass 1: logits + max ----
        int   s_nx = src[e0];
        float4 u_nx = U4[(size_t)s_nx * 32 + lane];
        for (int e = e0; e < e1; e++) {
            float4 u = u_nx;
            if (e + 1 < e1) {                       // prefetch next row
                int sn = src[e + 1];
                u_nx = U4[(size_t)sn * 32 + lane];
            }
            float q, z;
            q = u.x + v.x; z  = fmaxf(q, ALPHA_C * q) * a.x;
            q = u.y + v.y; z += fmaxf(q, ALPHA_C * q) * a.y;
            q = u.z + v.z; z += fmaxf(q, ALPHA_C * q) * a.z;
            q = u.w + v.w; z += fmaxf(q, ALPHA_C * q) * a.w;
            z += __shfl_xor_sync(0xffffffffu, z, 8);
            z += __shfl_xor_sync(0xffffffffu, z, 4);
            z += __shfl_xor_sync(0xffffffffu, z, 2);
            z += __shfl_xor_sync(0xffffffffu, z, 1);   // all lanes of half hold dot
            float l = z * INV_TEMP;
            m = fmaxf(m, l);
            int k = e - e0;
            if ((lane & 15) == 0) {
                if (k < 64) lbuf[wslot][h][k] = l;
                else        g_logits[2 * e + h] = l;
            }
        }
        __syncwarp();

        // ---- pass 2: exp-sum + weighted aggregate ----
        float s = 0.f;
        int   s2_nx = src[e0];
        float4 w_nx = Wh4[(size_t)s2_nx * 32 + lane];
        for (int e = e0; e < e1; e++) {
            float4 wv = w_nx;
            if (e + 1 < e1) {
                int sn = src[e + 1];
                w_nx = Wh4[(size_t)sn * 32 + lane];
            }
            int k = e - e0;
            float l = (k < 64) ? lbuf[wslot][h][k] : g_logits[2 * e + h];
            float w = __expf(l - m);
            s += w;
            acc.x = fmaf(w, wv.x, acc.x);
            acc.y = fmaf(w, wv.y, acc.y);
            acc.z = fmaf(w, wv.z, acc.z);
            acc.w = fmaf(w, wv.w, acc.w);
        }
        float inv = 1.0f / (s + 1e-9f);
        acc.x *= inv; acc.y *= inv; acc.z *= inv; acc.w *= inv;
    }

    // mean over heads: lane l<16 combines with lane l+16 (same channels)
    float bx = __shfl_down_sync(0xffffffffu, acc.x, 16);
    float by = __shfl_down_sync(0xffffffffu, acc.y, 16);
    float bz = __shfl_down_sync(0xffffffffu, acc.z, 16);
    float bw = __shfl_down_sync(0xffffffffu, acc.w, 16);
    if (lane < 16) {
        float4 r = make_float4((acc.x + bx) * 0.5f, (acc.y + by) * 0.5f,
                               (acc.z + bz) * 0.5f, (acc.w + bw) * 0.5f);
        ((float4*)out)[(size_t)n * 16 + lane] = r;
    }
}

// ---------------------------------------------------------------------------
extern "C" void kernel_launch(void* const* d_in, const int* in_sizes, int n_in,
                              void* d_out, int out_size) {
    const float* x     = (const float*)d_in[0];
    const float* W     = (const float*)d_in[1];
    const float* Wattn = (const float*)d_in[2];
    const float* avec  = (const float*)d_in[3];
    const int*   src   = (const int*)d_in[4];
    const int*   dst   = (const int*)d_in[5];
    float* out = (float*)d_out;
    int N = in_sizes[0] / INDIM;
    int E = in_sizes[4];

    k_rowptr<<<(E + 1 + 255) / 256, 256>>>(dst, E, N);
    k_gemm_wh<<<(N + 127) / 128, 256>>>(x, W, N);
    k_gemm_uv<<<dim3((N + 127) / 128, 4), 256>>>(Wattn, N);
    k_edge_fused<<<(N + 7) / 8, 256>>>(avec, src, out, N);
}

// round 7
// speedup vs baseline: 1.4637x; 1.3853x over previous
#include <cuda_runtime.h>
#include <cuda_bf16.h>
#include <cstdint>

// Problem constants
#define NN 50000
#define EE 400000
#define INDIM 256
#define HDIM 128
#define ALPHA_C 0.2f
#define INV_TEMP (1.0f / 0.55f)
#define ASTRIDE 72            // bf16 elems per smem row (144B: conflict-free ldmatrix)

// Scratch (device globals)
__device__ float g_Wh[NN * HDIM];
__device__ float g_U[NN * HDIM];
__device__ float g_V[NN * HDIM];
__device__ float g_logits[EE * 2];
__device__ int   g_rowptr[NN + 1];
// B fragments in native mma register layout (bf16x2 words):
// g_WB : [leg2][kt16][nt16][lane32][reg2]   (K1: W  -> 128KB)
__device__ uint32_t g_WB[32768];
// g_WaB: [leg2][q4][kt4][nt8][lane32][reg2] (K2: Wa -> 64KB)
__device__ uint32_t g_WaB[16384];

// ---------------- helpers ----------------
__device__ __forceinline__ uint32_t su32(const void* p) {
    uint32_t a;
    asm("{ .reg .u64 t; cvta.to.shared.u64 t, %1; cvt.u32.u64 %0, t; }" : "=r"(a) : "l"(p));
    return a;
}
__device__ __forceinline__ void split2(float v, unsigned short& hi, unsigned short& lo) {
    __nv_bfloat16 b = __float2bfloat16_rn(v);
    hi = __bfloat16_as_ushort(b);
    lo = __bfloat16_as_ushort(__float2bfloat16_rn(v - __bfloat162float(b)));
}
__device__ __forceinline__ void mma_bf16(float* c, const uint32_t* a, uint32_t b0, uint32_t b1) {
    asm volatile(
        "mma.sync.aligned.m16n8k16.row.col.f32.bf16.bf16.f32 "
        "{%0,%1,%2,%3},{%4,%5,%6,%7},{%8,%9},{%0,%1,%2,%3};"
        : "+f"(c[0]), "+f"(c[1]), "+f"(c[2]), "+f"(c[3])
        : "r"(a[0]), "r"(a[1]), "r"(a[2]), "r"(a[3]), "r"(b0), "r"(b1));
}
__device__ __forceinline__ void ldmA(uint32_t* a, uint32_t addr) {
    asm volatile("ldmatrix.sync.aligned.m8n8.x4.shared.b16 {%0,%1,%2,%3}, [%4];"
        : "=r"(a[0]), "=r"(a[1]), "=r"(a[2]), "=r"(a[3]) : "r"(addr));
}

// ---------------------------------------------------------------------------
// K0: CSR row pointers from sorted dst.
// ---------------------------------------------------------------------------
__global__ void k_rowptr(const int* __restrict__ dst, int E, int N) {
    int e = blockIdx.x * blockDim.x + threadIdx.x;
    if (e > E) return;
    int cur  = (e < E) ? dst[e] : N;
    int prev = (e == 0) ? -1 : dst[e - 1];
    for (int n = prev + 1; n <= cur; n++) g_rowptr[n] = e;
}

// ---------------------------------------------------------------------------
// Prep W -> B fragments. idx = [kt16][nt16][lane32][reg2]; value packs
// (W[k0][n], W[k0+1][n]) with k0 = kt*16 + reg*8 + cc*2, n = nt*8 + g.
// ---------------------------------------------------------------------------
__global__ void k_prep_w(const float* __restrict__ W) {
    int idx = blockIdx.x * 256 + threadIdx.x;    // 0..16383
    int reg = idx & 1, lane = (idx >> 1) & 31, nt = (idx >> 6) & 15, kt = idx >> 10;
    int cc = lane & 3, g = lane >> 2;
    int k0 = kt * 16 + reg * 8 + cc * 2;
    int n  = nt * 8 + g;
    unsigned short h0, l0, h1, l1;
    split2(W[(size_t)k0 * HDIM + n], h0, l0);
    split2(W[(size_t)(k0 + 1) * HDIM + n], h1, l1);
    g_WB[idx]         = ((uint32_t)h1 << 16) | h0;
    g_WB[16384 + idx] = ((uint32_t)l1 << 16) | l0;
}

// ---------------------------------------------------------------------------
// Prep Wa -> B fragments. idx = [q4][kt4][nt8][lane32][reg2].
// B(k=f, n=c) = Wa[h][p*64+f][c], h=q&1, p=q>>1.
// ---------------------------------------------------------------------------
__global__ void k_prep_wa(const float* __restrict__ Wa) {
    int idx = blockIdx.x * 256 + threadIdx.x;    // 0..8191
    int reg = idx & 1, lane = (idx >> 1) & 31, nt = (idx >> 6) & 7;
    int kt = (idx >> 9) & 3, q = idx >> 11;
    int cc = lane & 3, g = lane >> 2;
    int h = q & 1, p = q >> 1;
    int f0 = kt * 16 + reg * 8 + cc * 2;
    int n  = nt * 8 + g;
    unsigned short h0, l0, h1, l1;
    split2(Wa[h * 8192 + (p * 64 + f0) * 64 + n], h0, l0);
    split2(Wa[h * 8192 + (p * 64 + f0 + 1) * 64 + n], h1, l1);
    g_WaB[idx]        = ((uint32_t)h1 << 16) | h0;
    g_WaB[8192 + idx] = ((uint32_t)l1 << 16) | l0;
}

// ---------------------------------------------------------------------------
// K1: Wh = x @ W via mma.sync bf16 3-term. 128 rows/CTA, 8 warps (4m x 2n),
// K chunked by 64. A hi/lo staged in smem (stride-72 rows, conflict-free).
// ---------------------------------------------------------------------------
__global__ __launch_bounds__(256) void k_wh_mma(const float* __restrict__ x, int N) {
    __shared__ __align__(16) __nv_bfloat16 Ahi[128 * ASTRIDE];
    __shared__ __align__(16) __nv_bfloat16 Alo[128 * ASTRIDE];
    int tid = threadIdx.x, wid = tid >> 5, lane = tid & 31;
    int bm = blockIdx.x * 128;
    int wm = wid & 3, wn = wid >> 2;
    uint32_t ah_b = su32(Ahi), al_b = su32(Alo);

    float acc[2][8][4];
#pragma unroll
    for (int mt = 0; mt < 2; mt++)
#pragma unroll
        for (int nt = 0; nt < 8; nt++)
#pragma unroll
            for (int r = 0; r < 4; r++) acc[mt][nt][r] = 0.f;

    int lrow = lane & 15, lch = (lane >> 4) * 8;

    for (int kc = 0; kc < 4; kc++) {
        // stage A chunk: 128 rows x 64 k, split hi/lo
#pragma unroll
        for (int i = 0; i < 8; i++) {
            int c = tid + i * 256;               // 0..2047
            int row = c >> 4, kq = (c & 15) * 4;
            int gr = bm + row;
            float4 v = make_float4(0.f, 0.f, 0.f, 0.f);
            if (gr < N) v = *(const float4*)(x + (size_t)gr * INDIM + kc * 64 + kq);
            unsigned short hx, lx, hy, ly, hz, lz, hw, lw;
            split2(v.x, hx, lx); split2(v.y, hy, ly);
            split2(v.z, hz, lz); split2(v.w, hw, lw);
            *(uint2*)&Ahi[row * ASTRIDE + kq] =
                make_uint2(((uint32_t)hy << 16) | hx, ((uint32_t)hw << 16) | hz);
            *(uint2*)&Alo[row * ASTRIDE + kq] =
                make_uint2(((uint32_t)ly << 16) | lx, ((uint32_t)lw << 16) | lz);
        }
        __syncthreads();

#pragma unroll
        for (int kk = 0; kk < 4; kk++) {
            uint32_t afh[2][4], afl[2][4];
#pragma unroll
            for (int mt = 0; mt < 2; mt++) {
                uint32_t off = ((wm * 32 + mt * 16 + lrow) * ASTRIDE + kk * 16 + lch) * 2;
                ldmA(afh[mt], ah_b + off);
                ldmA(afl[mt], al_b + off);
            }
            int kt = kc * 4 + kk;
            const uint32_t* Bp = g_WB + (size_t)(kt * 16 + wn * 8) * 64 + lane * 2;
#pragma unroll
            for (int nt = 0; nt < 8; nt++) {
                uint2 bh = *(const uint2*)(Bp + nt * 64);
                uint2 bl = *(const uint2*)(Bp + nt * 64 + 16384);
#pragma unroll
                for (int mt = 0; mt < 2; mt++) {
                    mma_bf16(acc[mt][nt], afh[mt], bh.x, bh.y);
                    mma_bf16(acc[mt][nt], afh[mt], bl.x, bl.y);
                    mma_bf16(acc[mt][nt], afl[mt], bh.x, bh.y);
                }
            }
        }
        __syncthreads();
    }

    int g = lane >> 2, cc = lane & 3;
#pragma unroll
    for (int mt = 0; mt < 2; mt++)
#pragma unroll
        for (int nt = 0; nt < 8; nt++) {
            int row0 = bm + wm * 32 + mt * 16 + g;
            int col = wn * 64 + nt * 8 + cc * 2;
            if (row0 < N)
                *(float2*)(g_Wh + (size_t)row0 * HDIM + col) =
                    make_float2(acc[mt][nt][0], acc[mt][nt][1]);
            if (row0 + 8 < N)
                *(float2*)(g_Wh + (size_t)(row0 + 8) * HDIM + col) =
                    make_float2(acc[mt][nt][2], acc[mt][nt][3]);
        }
}

// ---------------------------------------------------------------------------
// K2: U/V = Wh_h @ Wa via mma.sync bf16 3-term. 64 rows/CTA, 8 warps:
// warp -> q = wid>>1 (p,h block), nh = wid&1 (32-col half). K=64 resident.
// ---------------------------------------------------------------------------
__global__ __launch_bounds__(256) void k_uv_mma(int N) {
    __shared__ __align__(16) __nv_bfloat16 A[2][2][64 * ASTRIDE];  // [h][leg]
    int tid = threadIdx.x, wid = tid >> 5, lane = tid & 31;
    int bm = blockIdx.x * 64;

#pragma unroll
    for (int i = 0; i < 8; i++) {
        int c = tid + i * 256;                   // 0..2047
        int row = c >> 5, kq = (c & 31) * 4;
        int h = kq >> 6, kl = kq & 63;
        int gr = bm + row;
        float4 v = make_float4(0.f, 0.f, 0.f, 0.f);
        if (gr < N) v = *(const float4*)(g_Wh + (size_t)gr * HDIM + kq);
        unsigned short hx, lx, hy, ly, hz, lz, hw, lw;
        split2(v.x, hx, lx); split2(v.y, hy, ly);
        split2(v.z, hz, lz); split2(v.w, hw, lw);
        *(uint2*)&A[h][0][row * ASTRIDE + kl] =
            make_uint2(((uint32_t)hy << 16) | hx, ((uint32_t)hw << 16) | hz);
        *(uint2*)&A[h][1][row * ASTRIDE + kl] =
            make_uint2(((uint32_t)ly << 16) | lx, ((uint32_t)lw << 16) | lz);
    }
    __syncthreads();

    int q = wid >> 1, nh = wid & 1, h = q & 1;
    uint32_t ah_b = su32(A[h][0]), al_b = su32(A[h][1]);
    float acc[4][4][4];
#pragma unroll
    for (int mt = 0; mt < 4; mt++)
#pragma unroll
        for (int nt = 0; nt < 4; nt++)
#pragma unroll
            for (int r = 0; r < 4; r++) acc[mt][nt][r] = 0.f;

    int lrow = lane & 15, lch = (lane >> 4) * 8;
#pragma unroll
    for (int kk = 0; kk < 4; kk++) {
        uint32_t afh[4][4], afl[4][4];
#pragma unroll
        for (int mt = 0; mt < 4; mt++) {
            uint32_t off = ((mt * 16 + lrow) * ASTRIDE + kk * 16 + lch) * 2;
            ldmA(afh[mt], ah_b + off);
            ldmA(afl[mt], al_b + off);
        }
        const uint32_t* Bp = g_WaB + (size_t)((q * 4 + kk) * 8 + nh * 4) * 64 + lane * 2;
#pragma unroll
        for (int nt = 0; nt < 4; nt++) {
            uint2 bh = *(const uint2*)(Bp + nt * 64);
            uint2 bl = *(const uint2*)(Bp + nt * 64 + 8192);
#pragma unroll
            for (int mt = 0; mt < 4; mt++) {
                mma_bf16(acc[mt][nt], afh[mt], bh.x, bh.y);
                mma_bf16(acc[mt][nt], afh[mt], bl.x, bl.y);
                mma_bf16(acc[mt][nt], afl[mt], bh.x, bh.y);
            }
        }
    }

    float* base = (q >> 1) ? g_V : g_U;
    int g = lane >> 2, cc = lane & 3;
#pragma unroll
    for (int mt = 0; mt < 4; mt++)
#pragma unroll
        for (int nt = 0; nt < 4; nt++) {
            int row0 = bm + mt * 16 + g;
            int col = h * 64 + nh * 32 + nt * 8 + cc * 2;
            if (row0 < N)
                *(float2*)(base + (size_t)row0 * HDIM + col) =
                    make_float2(acc[mt][nt][0], acc[mt][nt][1]);
            if (row0 + 8 < N)
                *(float2*)(base + (size_t)(row0 + 8) * HDIM + col) =
                    make_float2(acc[mt][nt][2], acc[mt][nt][3]);
        }
}

// ---------------------------------------------------------------------------
// K3 (fused logits + softmax + aggregate): one warp per dst node. (unchanged)
// ---------------------------------------------------------------------------
__global__ __launch_bounds__(256) void k_edge_fused(const float* __restrict__ avec,
                                                    const int* __restrict__ src,
                                                    float* __restrict__ out, int N) {
    __shared__ float lbuf[8][2][64];
    int t = blockIdx.x * blockDim.x + threadIdx.x;
    int n = t >> 5, lane = t & 31;
    if (n >= N) return;
    int wslot = threadIdx.x >> 5;
    int e0 = g_rowptr[n], e1 = g_rowptr[n + 1];
    int h = lane >> 4;
    const float4* U4  = (const float4*)g_U;
    const float4* V4  = (const float4*)g_V;
    const float4* Wh4 = (const float4*)g_Wh;
    float4 a = ((const float4*)avec)[lane];
    float4 acc = make_float4(0.f, 0.f, 0.f, 0.f);

    if (e1 > e0) {
        float4 v = V4[(size_t)n * 32 + lane];
        float m = -1e30f;
        int   s_nx = src[e0];
        float4 u_nx = U4[(size_t)s_nx * 32 + lane];
        for (int e = e0; e < e1; e++) {
            float4 u = u_nx;
            if (e + 1 < e1) {
                int sn = src[e + 1];
                u_nx = U4[(size_t)sn * 32 + lane];
            }
            float q, z;
            q = u.x + v.x; z  = fmaxf(q, ALPHA_C * q) * a.x;
            q = u.y + v.y; z += fmaxf(q, ALPHA_C * q) * a.y;
            q = u.z + v.z; z += fmaxf(q, ALPHA_C * q) * a.z;
            q = u.w + v.w; z += fmaxf(q, ALPHA_C * q) * a.w;
            z += __shfl_xor_sync(0xffffffffu, z, 8);
            z += __shfl_xor_sync(0xffffffffu, z, 4);
            z += __shfl_xor_sync(0xffffffffu, z, 2);
            z += __shfl_xor_sync(0xffffffffu, z, 1);
            float l = z * INV_TEMP;
            m = fmaxf(m, l);
            int k = e - e0;
            if ((lane & 15) == 0) {
                if (k < 64) lbuf[wslot][h][k] = l;
                else        g_logits[2 * e + h] = l;
            }
        }
        __syncwarp();
        float s = 0.f;
        int   s2_nx = src[e0];
        float4 w_nx = Wh4[(size_t)s2_nx * 32 + lane];
        for (int e = e0; e < e1; e++) {
            float4 wv = w_nx;
            if (e + 1 < e1) {
                int sn = src[e + 1];
                w_nx = Wh4[(size_t)sn * 32 + lane];
            }
            int k = e - e0;
            float l = (k < 64) ? lbuf[wslot][h][k] : g_logits[2 * e + h];
            float w = __expf(l - m);
            s += w;
            acc.x = fmaf(w, wv.x, acc.x);
            acc.y = fmaf(w, wv.y, acc.y);
            acc.z = fmaf(w, wv.z, acc.z);
            acc.w = fmaf(w, wv.w, acc.w);
        }
        float inv = 1.0f / (s + 1e-9f);
        acc.x *= inv; acc.y *= inv; acc.z *= inv; acc.w *= inv;
    }
    float bx = __shfl_down_sync(0xffffffffu, acc.x, 16);
    float by = __shfl_down_sync(0xffffffffu, acc.y, 16);
    float bz = __shfl_down_sync(0xffffffffu, acc.z, 16);
    float bw = __shfl_down_sync(0xffffffffu, acc.w, 16);
    if (lane < 16) {
        float4 r = make_float4((acc.x + bx) * 0.5f, (acc.y + by) * 0.5f,
                               (acc.z + bz) * 0.5f, (acc.w + bw) * 0.5f);
        ((float4*)out)[(size_t)n * 16 + lane] = r;
    }
}

// ---------------------------------------------------------------------------
extern "C" void kernel_launch(void* const* d_in, const int* in_sizes, int n_in,
                              void* d_out, int out_size) {
    const float* x     = (const float*)d_in[0];
    const float* W     = (const float*)d_in[1];
    const float* Wattn = (const float*)d_in[2];
    const float* avec  = (const float*)d_in[3];
    const int*   src   = (const int*)d_in[4];
    const int*   dst   = (const int*)d_in[5];
    float* out = (float*)d_out;
    int N = in_sizes[0] / INDIM;
    int E = in_sizes[4];

    k_rowptr<<<(E + 1 + 255) / 256, 256>>>(dst, E, N);
    k_prep_w<<<64, 256>>>(W);
    k_prep_wa<<<32, 256>>>(Wattn);
    k_wh_mma<<<(N + 127) / 128, 256>>>(x, N);
    k_uv_mma<<<(N + 63) / 64, 256>>>(N);
    k_edge_fused<<<(N + 7) / 8, 256>>>(avec, src, out, N);
}

// round 9
// speedup vs baseline: 1.9006x; 1.2986x over previous
#include <cuda_runtime.h>
#include <cuda_bf16.h>
#include <cstdint>

// Problem constants
#define NN 50000
#define EE 400000
#define INDIM 256
#define HDIM 128
#define ALPHA_C 0.2f
#define INV_TEMP (1.0f / 0.55f)
#define ASTRIDE 72            // bf16 elems per smem row (144B: conflict-free ldmatrix)

// Scratch (device globals)
__device__ float g_Wh[NN * HDIM];
__device__ float g_U[NN * HDIM];
__device__ float g_V[NN * HDIM];
__device__ float g_logits[EE * 2];
__device__ int   g_rowptr[NN + 1];
// B fragments in native mma register layout (bf16x2 words):
// g_WB : [leg2][kt16][nt16][lane32][reg2]   (K1: W  -> 128KB)
__device__ uint32_t g_WB[32768];
// g_WaB: [leg2][q4][kt4][nt8][lane32][reg2] (K2: Wa -> 64KB)
__device__ uint32_t g_WaB[16384];

// ---------------- helpers ----------------
__device__ __forceinline__ uint32_t su32(const void* p) {
    uint32_t a;
    asm("{ .reg .u64 t; cvta.to.shared.u64 t, %1; cvt.u32.u64 %0, t; }" : "=r"(a) : "l"(p));
    return a;
}
__device__ __forceinline__ void split2(float v, unsigned short& hi, unsigned short& lo) {
    __nv_bfloat16 b = __float2bfloat16_rn(v);
    hi = __bfloat16_as_ushort(b);
    lo = __bfloat16_as_ushort(__float2bfloat16_rn(v - __bfloat162float(b)));
}
__device__ __forceinline__ void mma_bf16(float* c, const uint32_t* a, uint32_t b0, uint32_t b1) {
    asm volatile(
        "mma.sync.aligned.m16n8k16.row.col.f32.bf16.bf16.f32 "
        "{%0,%1,%2,%3},{%4,%5,%6,%7},{%8,%9},{%0,%1,%2,%3};"
        : "+f"(c[0]), "+f"(c[1]), "+f"(c[2]), "+f"(c[3])
        : "r"(a[0]), "r"(a[1]), "r"(a[2]), "r"(a[3]), "r"(b0), "r"(b1));
}
__device__ __forceinline__ void ldmA(uint32_t* a, uint32_t addr) {
    asm volatile("ldmatrix.sync.aligned.m8n8.x4.shared.b16 {%0,%1,%2,%3}, [%4];"
        : "=r"(a[0]), "=r"(a[1]), "=r"(a[2]), "=r"(a[3]) : "r"(addr));
}

// ---------------------------------------------------------------------------
// K0: CSR row pointers from sorted dst.
// ---------------------------------------------------------------------------
__global__ void k_rowptr(const int* __restrict__ dst, int E, int N) {
    int e = blockIdx.x * blockDim.x + threadIdx.x;
    if (e > E) return;
    int cur  = (e < E) ? dst[e] : N;
    int prev = (e == 0) ? -1 : dst[e - 1];
    for (int n = prev + 1; n <= cur; n++) g_rowptr[n] = e;
}

// ---------------------------------------------------------------------------
// Prep W -> B fragments. idx = [kt16][nt16][lane32][reg2]; value packs
// (W[k0][n], W[k0+1][n]) with k0 = kt*16 + reg*8 + cc*2, n = nt*8 + g.
// ---------------------------------------------------------------------------
__global__ void k_prep_w(const float* __restrict__ W) {
    int idx = blockIdx.x * 256 + threadIdx.x;    // 0..16383
    int reg = idx & 1, lane = (idx >> 1) & 31, nt = (idx >> 6) & 15, kt = idx >> 10;
    int cc = lane & 3, g = lane >> 2;
    int k0 = kt * 16 + reg * 8 + cc * 2;
    int n  = nt * 8 + g;
    unsigned short h0, l0, h1, l1;
    split2(W[(size_t)k0 * HDIM + n], h0, l0);
    split2(W[(size_t)(k0 + 1) * HDIM + n], h1, l1);
    g_WB[idx]         = ((uint32_t)h1 << 16) | h0;
    g_WB[16384 + idx] = ((uint32_t)l1 << 16) | l0;
}

// ---------------------------------------------------------------------------
// Prep Wa -> B fragments. idx = [q4][kt4][nt8][lane32][reg2].
// B(k=f, n=c) = Wa[h][p*64+f][c], h=q&1, p=q>>1.
// ---------------------------------------------------------------------------
__global__ void k_prep_wa(const float* __restrict__ Wa) {
    int idx = blockIdx.x * 256 + threadIdx.x;    // 0..8191
    int reg = idx & 1, lane = (idx >> 1) & 31, nt = (idx >> 6) & 7;
    int kt = (idx >> 9) & 3, q = idx >> 11;
    int cc = lane & 3, g = lane >> 2;
    int h = q & 1, p = q >> 1;
    int f0 = kt * 16 + reg * 8 + cc * 2;
    int n  = nt * 8 + g;
    unsigned short h0, l0, h1, l1;
    split2(Wa[h * 8192 + (p * 64 + f0) * 64 + n], h0, l0);
    split2(Wa[h * 8192 + (p * 64 + f0 + 1) * 64 + n], h1, l1);
    g_WaB[idx]        = ((uint32_t)h1 << 16) | h0;
    g_WaB[8192 + idx] = ((uint32_t)l1 << 16) | l0;
}

// ---------------------------------------------------------------------------
// K1: Wh = x @ W via mma.sync bf16 3-term. 64 rows/CTA, 8 warps (2m x 4n),
// K chunked by 64. A hi/lo staged in smem (stride-72 rows, conflict-free).
// Small tile + reg cap -> 2 CTAs/SM for latency hiding (R7 was occ-starved).
// ---------------------------------------------------------------------------
__global__ __launch_bounds__(256, 2) void k_wh_mma(const float* __restrict__ x, int N) {
    __shared__ __align__(16) __nv_bfloat16 Ahi[64 * ASTRIDE];
    __shared__ __align__(16) __nv_bfloat16 Alo[64 * ASTRIDE];
    int tid = threadIdx.x, wid = tid >> 5, lane = tid & 31;
    int bm = blockIdx.x * 64;
    int wm = wid & 1, wn = wid >> 1;          // 2 m-groups x 4 n-groups
    uint32_t ah_b = su32(Ahi), al_b = su32(Alo);

    float acc[2][4][4];
#pragma unroll
    for (int mt = 0; mt < 2; mt++)
#pragma unroll
        for (int nt = 0; nt < 4; nt++)
#pragma unroll
            for (int r = 0; r < 4; r++) acc[mt][nt][r] = 0.f;

    int lrow = lane & 15, lch = (lane >> 4) * 8;

    for (int kc = 0; kc < 4; kc++) {
        // stage A chunk: 64 rows x 64 k, split hi/lo (1024 float4, 4/thread)
#pragma unroll
        for (int i = 0; i < 4; i++) {
            int c = tid + i * 256;               // 0..1023
            int row = c >> 4, kq = (c & 15) * 4;
            int gr = bm + row;
            float4 v = make_float4(0.f, 0.f, 0.f, 0.f);
            if (gr < N) v = *(const float4*)(x + (size_t)gr * INDIM + kc * 64 + kq);
            unsigned short hx, lx, hy, ly, hz, lz, hw, lw;
            split2(v.x, hx, lx); split2(v.y, hy, ly);
            split2(v.z, hz, lz); split2(v.w, hw, lw);
            *(uint2*)&Ahi[row * ASTRIDE + kq] =
                make_uint2(((uint32_t)hy << 16) | hx, ((uint32_t)hw << 16) | hz);
            *(uint2*)&Alo[row * ASTRIDE + kq] =
                make_uint2(((uint32_t)ly << 16) | lx, ((uint32_t)lw << 16) | lz);
        }
        __syncthreads();

#pragma unroll
        for (int kk = 0; kk < 4; kk++) {
            uint32_t afh[2][4], afl[2][4];
#pragma unroll
            for (int mt = 0; mt < 2; mt++) {
                uint32_t off = ((wm * 32 + mt * 16 + lrow) * ASTRIDE + kk * 16 + lch) * 2;
                ldmA(afh[mt], ah_b + off);
                ldmA(afl[mt], al_b + off);
            }
            int kt = kc * 4 + kk;
            const uint32_t* Bp = g_WB + (size_t)(kt * 16 + wn * 4) * 64 + lane * 2;
#pragma unroll
            for (int nt = 0; nt < 4; nt++) {
                uint2 bh = *(const uint2*)(Bp + nt * 64);
                uint2 bl = *(const uint2*)(Bp + nt * 64 + 16384);
#pragma unroll
                for (int mt = 0; mt < 2; mt++) {
                    mma_bf16(acc[mt][nt], afh[mt], bh.x, bh.y);
                    mma_bf16(acc[mt][nt], afh[mt], bl.x, bl.y);
                    mma_bf16(acc[mt][nt], afl[mt], bh.x, bh.y);
                }
            }
        }
        __syncthreads();
    }

    int g = lane >> 2, cc = lane & 3;
#pragma unroll
    for (int mt = 0; mt < 2; mt++)
#pragma unroll
        for (int nt = 0; nt < 4; nt++) {
            int row0 = bm + wm * 32 + mt * 16 + g;
            int col = wn * 32 + nt * 8 + cc * 2;
            if (row0 < N)
                *(float2*)(g_Wh + (size_t)row0 * HDIM + col) =
                    make_float2(acc[mt][nt][0], acc[mt][nt][1]);
            if (row0 + 8 < N)
                *(float2*)(g_Wh + (size_t)(row0 + 8) * HDIM + col) =
                    make_float2(acc[mt][nt][2], acc[mt][nt][3]);
        }
}

// ---------------------------------------------------------------------------
// K2: U/V = Wh_h @ Wa via mma.sync bf16 3-term. 64 rows/CTA, 8 warps:
// warp -> q = wid>>1 (p,h block), nh = wid&1 (32-col half). K=64 resident.
// ---------------------------------------------------------------------------
__global__ __launch_bounds__(256) void k_uv_mma(int N) {
    __shared__ __align__(16) __nv_bfloat16 A[2][2][64 * ASTRIDE];  // [h][leg]
    int tid = threadIdx.x, wid = tid >> 5, lane = tid & 31;
    int bm = blockIdx.x * 64;

#pragma unroll
    for (int i = 0; i < 8; i++) {
        int c = tid + i * 256;                   // 0..2047
        int row = c >> 5, kq = (c & 31) * 4;
        int h = kq >> 6, kl = kq & 63;
        int gr = bm + row;
        float4 v = make_float4(0.f, 0.f, 0.f, 0.f);
        if (gr < N) v = *(const float4*)(g_Wh + (size_t)gr * HDIM + kq);
        unsigned short hx, lx, hy, ly, hz, lz, hw, lw;
        split2(v.x, hx, lx); split2(v.y, hy, ly);
        split2(v.z, hz, lz); split2(v.w, hw, lw);
        *(uint2*)&A[h][0][row * ASTRIDE + kl] =
            make_uint2(((uint32_t)hy << 16) | hx, ((uint32_t)hw << 16) | hz);
        *(uint2*)&A[h][1][row * ASTRIDE + kl] =
            make_uint2(((uint32_t)ly << 16) | lx, ((uint32_t)lw << 16) | lz);
    }
    __syncthreads();

    int q = wid >> 1, nh = wid & 1, h = q & 1;
    uint32_t ah_b = su32(A[h][0]), al_b = su32(A[h][1]);
    float acc[4][4][4];
#pragma unroll
    for (int mt = 0; mt < 4; mt++)
#pragma unroll
        for (int nt = 0; nt < 4; nt++)
#pragma unroll
            for (int r = 0; r < 4; r++) acc[mt][nt][r] = 0.f;

    int lrow = lane & 15, lch = (lane >> 4) * 8;
#pragma unroll
    for (int kk = 0; kk < 4; kk++) {
        uint32_t afh[4][4], afl[4][4];
#pragma unroll
        for (int mt = 0; mt < 4; mt++) {
            uint32_t off = ((mt * 16 + lrow) * ASTRIDE + kk * 16 + lch) * 2;
            ldmA(afh[mt], ah_b + off);
            ldmA(afl[mt], al_b + off);
        }
        const uint32_t* Bp = g_WaB + (size_t)((q * 4 + kk) * 8 + nh * 4) * 64 + lane * 2;
#pragma unroll
        for (int nt = 0; nt < 4; nt++) {
            uint2 bh = *(const uint2*)(Bp + nt * 64);
            uint2 bl = *(const uint2*)(Bp + nt * 64 + 8192);
#pragma unroll
            for (int mt = 0; mt < 4; mt++) {
                mma_bf16(acc[mt][nt], afh[mt], bh.x, bh.y);
                mma_bf16(acc[mt][nt], afh[mt], bl.x, bl.y);
                mma_bf16(acc[mt][nt], afl[mt], bh.x, bh.y);
            }
        }
    }

    float* base = (q >> 1) ? g_V : g_U;
    int g = lane >> 2, cc = lane & 3;
#pragma unroll
    for (int mt = 0; mt < 4; mt++)
#pragma unroll
        for (int nt = 0; nt < 4; nt++) {
            int row0 = bm + mt * 16 + g;
            int col = h * 64 + nh * 32 + nt * 8 + cc * 2;
            if (row0 < N)
                *(float2*)(base + (size_t)row0 * HDIM + col) =
                    make_float2(acc[mt][nt][0], acc[mt][nt][1]);
            if (row0 + 8 < N)
                *(float2*)(base + (size_t)(row0 + 8) * HDIM + col) =
                    make_float2(acc[mt][nt][2], acc[mt][nt][3]);
        }
}

// ---------------------------------------------------------------------------
// K3 (fused logits + softmax + aggregate): one warp per dst node. (unchanged)
// ---------------------------------------------------------------------------
__global__ __launch_bounds__(256) void k_edge_fused(const float* __restrict__ avec,
                                                    const int* __restrict__ src,
                                                    float* __restrict__ out, int N) {
    __shared__ float lbuf[8][2][64];
    int t = blockIdx.x * blockDim.x + threadIdx.x;
    int n = t >> 5, lane = t & 31;
    if (n >= N) return;
    int wslot = threadIdx.x >> 5;
    int e0 = g_rowptr[n], e1 = g_rowptr[n + 1];
    int h = lane >> 4;
    const float4* U4  = (const float4*)g_U;
    const float4* V4  = (const float4*)g_V;
    const float4* Wh4 = (const float4*)g_Wh;
    float4 a = ((const float4*)avec)[lane];
    float4 acc = make_float4(0.f, 0.f, 0.f, 0.f);

    if (e1 > e0) {
        float4 v = V4[(size_t)n * 32 + lane];
        float m = -1e30f;
        int   s_nx = src[e0];
        float4 u_nx = U4[(size_t)s_nx * 32 + lane];
        for (int e = e0; e < e1; e++) {
            float4 u = u_nx;
            if (e + 1 < e1) {
                int sn = src[e + 1];
                u_nx = U4[(size_t)sn * 32 + lane];
            }
            float q, z;
            q = u.x + v.x; z  = fmaxf(q, ALPHA_C * q) * a.x;
            q = u.y + v.y; z += fmaxf(q, ALPHA_C * q) * a.y;
            q = u.z + v.z; z += fmaxf(q, ALPHA_C * q) * a.z;
            q = u.w + v.w; z += fmaxf(q, ALPHA_C * q) * a.w;
            z += __shfl_xor_sync(0xffffffffu, z, 8);
            z += __shfl_xor_sync(0xffffffffu, z, 4);
            z += __shfl_xor_sync(0xffffffffu, z, 2);
            z += __shfl_xor_sync(0xffffffffu, z, 1);
            float l = z * INV_TEMP;
            m = fmaxf(m, l);
            int k = e - e0;
            if ((lane & 15) == 0) {
                if (k < 64) lbuf[wslot][h][k] = l;
                else        g_logits[2 * e + h] = l;
            }
        }
        __syncwarp();
        float s = 0.f;
        int   s2_nx = src[e0];
        float4 w_nx = Wh4[(size_t)s2_nx * 32 + lane];
        for (int e = e0; e < e1; e++) {
            float4 wv = w_nx;
            if (e + 1 < e1) {
                int sn = src[e + 1];
                w_nx = Wh4[(size_t)sn * 32 + lane];
            }
            int k = e - e0;
            float l = (k < 64) ? lbuf[wslot][h][k] : g_logits[2 * e + h];
            float w = __expf(l - m);
            s += w;
            acc.x = fmaf(w, wv.x, acc.x);
            acc.y = fmaf(w, wv.y, acc.y);
            acc.z = fmaf(w, wv.z, acc.z);
            acc.w = fmaf(w, wv.w, acc.w);
        }
        float inv = 1.0f / (s + 1e-9f);
        acc.x *= inv; acc.y *= inv; acc.z *= inv; acc.w *= inv;
    }
    float bx = __shfl_down_sync(0xffffffffu, acc.x, 16);
    float by = __shfl_down_sync(0xffffffffu, acc.y, 16);
    float bz = __shfl_down_sync(0xffffffffu, acc.z, 16);
    float bw = __shfl_down_sync(0xffffffffu, acc.w, 16);
    if (lane < 16) {
        float4 r = make_float4((acc.x + bx) * 0.5f, (acc.y + by) * 0.5f,
                               (acc.z + bz) * 0.5f, (acc.w + bw) * 0.5f);
        ((float4*)out)[(size_t)n * 16 + lane] = r;
    }
}

// ---------------------------------------------------------------------------
extern "C" void kernel_launch(void* const* d_in, const int* in_sizes, int n_in,
                              void* d_out, int out_size) {
    const float* x     = (const float*)d_in[0];
    const float* W     = (const float*)d_in[1];
    const float* Wattn = (const float*)d_in[2];
    const float* avec  = (const float*)d_in[3];
    const int*   src   = (const int*)d_in[4];
    const int*   dst   = (const int*)d_in[5];
    float* out = (float*)d_out;
    int N = in_sizes[0] / INDIM;
    int E = in_sizes[4];

    k_rowptr<<<(E + 1 + 255) / 256, 256>>>(dst, E, N);
    k_prep_w<<<64, 256>>>(W);
    k_prep_wa<<<32, 256>>>(Wattn);
    k_wh_mma<<<(N + 63) / 64, 256>>>(x, N);
    k_uv_mma<<<(N + 63) / 64, 256>>>(N);
    k_edge_fused<<<(N + 7) / 8, 256>>>(avec, src, out, N);
}

// round 10
// speedup vs baseline: 2.0194x; 1.0625x over previous
#include <cuda_runtime.h>
#include <cuda_bf16.h>
#include <cstdint>

// Problem constants
#define NN 50000
#define EE 400000
#define INDIM 256
#define HDIM 128
#define ALPHA_C 0.2f
#define INV_TEMP (1.0f / 0.55f)
#define ASTRIDE 72            // bf16 elems per smem row (144B: conflict-free ldmatrix)

// Scratch (device globals)
__device__ float g_Wh[NN * HDIM];
__device__ float g_U[NN * HDIM];
__device__ float g_V[NN * HDIM];
__device__ int   g_rowptr[NN + 1];
// B fragments in native mma register layout (bf16x2 words):
// g_WB : [leg2][kt16][nt16][lane32][reg2]   (K1: W  -> 128KB)
__device__ uint32_t g_WB[32768];
// g_WaB: [leg2][q4][kt4][nt8][lane32][reg2] (K2: Wa -> 64KB)
__device__ uint32_t g_WaB[16384];

// ---------------- helpers ----------------
__device__ __forceinline__ uint32_t su32(const void* p) {
    uint32_t a;
    asm("{ .reg .u64 t; cvta.to.shared.u64 t, %1; cvt.u32.u64 %0, t; }" : "=r"(a) : "l"(p));
    return a;
}
__device__ __forceinline__ void split2(float v, unsigned short& hi, unsigned short& lo) {
    __nv_bfloat16 b = __float2bfloat16_rn(v);
    hi = __bfloat16_as_ushort(b);
    lo = __bfloat16_as_ushort(__float2bfloat16_rn(v - __bfloat162float(b)));
}
__device__ __forceinline__ void mma_bf16(float* c, const uint32_t* a, uint32_t b0, uint32_t b1) {
    asm volatile(
        "mma.sync.aligned.m16n8k16.row.col.f32.bf16.bf16.f32 "
        "{%0,%1,%2,%3},{%4,%5,%6,%7},{%8,%9},{%0,%1,%2,%3};"
        : "+f"(c[0]), "+f"(c[1]), "+f"(c[2]), "+f"(c[3])
        : "r"(a[0]), "r"(a[1]), "r"(a[2]), "r"(a[3]), "r"(b0), "r"(b1));
}
__device__ __forceinline__ void ldmA(uint32_t* a, uint32_t addr) {
    asm volatile("ldmatrix.sync.aligned.m8n8.x4.shared.b16 {%0,%1,%2,%3}, [%4];"
        : "=r"(a[0]), "=r"(a[1]), "=r"(a[2]), "=r"(a[3]) : "r"(addr));
}

// ---------------------------------------------------------------------------
// K0: CSR row pointers from sorted dst.
// ---------------------------------------------------------------------------
__global__ void k_rowptr(const int* __restrict__ dst, int E, int N) {
    int e = blockIdx.x * blockDim.x + threadIdx.x;
    if (e > E) return;
    int cur  = (e < E) ? dst[e] : N;
    int prev = (e == 0) ? -1 : dst[e - 1];
    for (int n = prev + 1; n <= cur; n++) g_rowptr[n] = e;
}

// ---------------------------------------------------------------------------
// Prep W -> B fragments. idx = [kt16][nt16][lane32][reg2].
// ---------------------------------------------------------------------------
__global__ void k_prep_w(const float* __restrict__ W) {
    int idx = blockIdx.x * 256 + threadIdx.x;    // 0..16383
    int reg = idx & 1, lane = (idx >> 1) & 31, nt = (idx >> 6) & 15, kt = idx >> 10;
    int cc = lane & 3, g = lane >> 2;
    int k0 = kt * 16 + reg * 8 + cc * 2;
    int n  = nt * 8 + g;
    unsigned short h0, l0, h1, l1;
    split2(W[(size_t)k0 * HDIM + n], h0, l0);
    split2(W[(size_t)(k0 + 1) * HDIM + n], h1, l1);
    g_WB[idx]         = ((uint32_t)h1 << 16) | h0;
    g_WB[16384 + idx] = ((uint32_t)l1 << 16) | l0;
}

// ---------------------------------------------------------------------------
// Prep Wa -> B fragments. idx = [q4][kt4][nt8][lane32][reg2].
// ---------------------------------------------------------------------------
__global__ void k_prep_wa(const float* __restrict__ Wa) {
    int idx = blockIdx.x * 256 + threadIdx.x;    // 0..8191
    int reg = idx & 1, lane = (idx >> 1) & 31, nt = (idx >> 6) & 7;
    int kt = (idx >> 9) & 3, q = idx >> 11;
    int cc = lane & 3, g = lane >> 2;
    int h = q & 1, p = q >> 1;
    int f0 = kt * 16 + reg * 8 + cc * 2;
    int n  = nt * 8 + g;
    unsigned short h0, l0, h1, l1;
    split2(Wa[h * 8192 + (p * 64 + f0) * 64 + n], h0, l0);
    split2(Wa[h * 8192 + (p * 64 + f0 + 1) * 64 + n], h1, l1);
    g_WaB[idx]        = ((uint32_t)h1 << 16) | h0;
    g_WaB[8192 + idx] = ((uint32_t)l1 << 16) | l0;
}

// ---------------------------------------------------------------------------
// K1: Wh = x @ W via mma.sync bf16 3-term. 64 rows/CTA, 8 warps (2m x 4n).
// ---------------------------------------------------------------------------
__global__ __launch_bounds__(256, 2) void k_wh_mma(const float* __restrict__ x, int N) {
    __shared__ __align__(16) __nv_bfloat16 Ahi[64 * ASTRIDE];
    __shared__ __align__(16) __nv_bfloat16 Alo[64 * ASTRIDE];
    int tid = threadIdx.x, wid = tid >> 5, lane = tid & 31;
    int bm = blockIdx.x * 64;
    int wm = wid & 1, wn = wid >> 1;
    uint32_t ah_b = su32(Ahi), al_b = su32(Alo);

    float acc[2][4][4];
#pragma unroll
    for (int mt = 0; mt < 2; mt++)
#pragma unroll
        for (int nt = 0; nt < 4; nt++)
#pragma unroll
            for (int r = 0; r < 4; r++) acc[mt][nt][r] = 0.f;

    int lrow = lane & 15, lch = (lane >> 4) * 8;

    for (int kc = 0; kc < 4; kc++) {
#pragma unroll
        for (int i = 0; i < 4; i++) {
            int c = tid + i * 256;
            int row = c >> 4, kq = (c & 15) * 4;
            int gr = bm + row;
            float4 v = make_float4(0.f, 0.f, 0.f, 0.f);
            if (gr < N) v = *(const float4*)(x + (size_t)gr * INDIM + kc * 64 + kq);
            unsigned short hx, lx, hy, ly, hz, lz, hw, lw;
            split2(v.x, hx, lx); split2(v.y, hy, ly);
            split2(v.z, hz, lz); split2(v.w, hw, lw);
            *(uint2*)&Ahi[row * ASTRIDE + kq] =
                make_uint2(((uint32_t)hy << 16) | hx, ((uint32_t)hw << 16) | hz);
            *(uint2*)&Alo[row * ASTRIDE + kq] =
                make_uint2(((uint32_t)ly << 16) | lx, ((uint32_t)lw << 16) | lz);
        }
        __syncthreads();

#pragma unroll
        for (int kk = 0; kk < 4; kk++) {
            uint32_t afh[2][4], afl[2][4];
#pragma unroll
            for (int mt = 0; mt < 2; mt++) {
                uint32_t off = ((wm * 32 + mt * 16 + lrow) * ASTRIDE + kk * 16 + lch) * 2;
                ldmA(afh[mt], ah_b + off);
                ldmA(afl[mt], al_b + off);
            }
            int kt = kc * 4 + kk;
            const uint32_t* Bp = g_WB + (size_t)(kt * 16 + wn * 4) * 64 + lane * 2;
#pragma unroll
            for (int nt = 0; nt < 4; nt++) {
                uint2 bh = *(const uint2*)(Bp + nt * 64);
                uint2 bl = *(const uint2*)(Bp + nt * 64 + 16384);
#pragma unroll
                for (int mt = 0; mt < 2; mt++) {
                    mma_bf16(acc[mt][nt], afh[mt], bh.x, bh.y);
                    mma_bf16(acc[mt][nt], afh[mt], bl.x, bl.y);
                    mma_bf16(acc[mt][nt], afl[mt], bh.x, bh.y);
                }
            }
        }
        __syncthreads();
    }

    int g = lane >> 2, cc = lane & 3;
#pragma unroll
    for (int mt = 0; mt < 2; mt++)
#pragma unroll
        for (int nt = 0; nt < 4; nt++) {
            int row0 = bm + wm * 32 + mt * 16 + g;
            int col = wn * 32 + nt * 8 + cc * 2;
            if (row0 < N)
                *(float2*)(g_Wh + (size_t)row0 * HDIM + col) =
                    make_float2(acc[mt][nt][0], acc[mt][nt][1]);
            if (row0 + 8 < N)
                *(float2*)(g_Wh + (size_t)(row0 + 8) * HDIM + col) =
                    make_float2(acc[mt][nt][2], acc[mt][nt][3]);
        }
}

// ---------------------------------------------------------------------------
// K2: U/V = Wh_h @ Wa via mma.sync bf16 3-term. 64 rows/CTA.
// ---------------------------------------------------------------------------
__global__ __launch_bounds__(256) void k_uv_mma(int N) {
    __shared__ __align__(16) __nv_bfloat16 A[2][2][64 * ASTRIDE];  // [h][leg]
    int tid = threadIdx.x, wid = tid >> 5, lane = tid & 31;
    int bm = blockIdx.x * 64;

#pragma unroll
    for (int i = 0; i < 8; i++) {
        int c = tid + i * 256;
        int row = c >> 5, kq = (c & 31) * 4;
        int h = kq >> 6, kl = kq & 63;
        int gr = bm + row;
        float4 v = make_float4(0.f, 0.f, 0.f, 0.f);
        if (gr < N) v = *(const float4*)(g_Wh + (size_t)gr * HDIM + kq);
        unsigned short hx, lx, hy, ly, hz, lz, hw, lw;
        split2(v.x, hx, lx); split2(v.y, hy, ly);
        split2(v.z, hz, lz); split2(v.w, hw, lw);
        *(uint2*)&A[h][0][row * ASTRIDE + kl] =
            make_uint2(((uint32_t)hy << 16) | hx, ((uint32_t)hw << 16) | hz);
        *(uint2*)&A[h][1][row * ASTRIDE + kl] =
            make_uint2(((uint32_t)ly << 16) | lx, ((uint32_t)lw << 16) | lz);
    }
    __syncthreads();

    int q = wid >> 1, nh = wid & 1, h = q & 1;
    uint32_t ah_b = su32(A[h][0]), al_b = su32(A[h][1]);
    float acc[4][4][4];
#pragma unroll
    for (int mt = 0; mt < 4; mt++)
#pragma unroll
        for (int nt = 0; nt < 4; nt++)
#pragma unroll
            for (int r = 0; r < 4; r++) acc[mt][nt][r] = 0.f;

    int lrow = lane & 15, lch = (lane >> 4) * 8;
#pragma unroll
    for (int kk = 0; kk < 4; kk++) {
        uint32_t afh[4][4], afl[4][4];
#pragma unroll
        for (int mt = 0; mt < 4; mt++) {
            uint32_t off = ((mt * 16 + lrow) * ASTRIDE + kk * 16 + lch) * 2;
            ldmA(afh[mt], ah_b + off);
            ldmA(afl[mt], al_b + off);
        }
        const uint32_t* Bp = g_WaB + (size_t)((q * 4 + kk) * 8 + nh * 4) * 64 + lane * 2;
#pragma unroll
        for (int nt = 0; nt < 4; nt++) {
            uint2 bh = *(const uint2*)(Bp + nt * 64);
            uint2 bl = *(const uint2*)(Bp + nt * 64 + 8192);
#pragma unroll
            for (int mt = 0; mt < 4; mt++) {
                mma_bf16(acc[mt][nt], afh[mt], bh.x, bh.y);
                mma_bf16(acc[mt][nt], afh[mt], bl.x, bl.y);
                mma_bf16(acc[mt][nt], afl[mt], bh.x, bh.y);
            }
        }
    }

    float* base = (q >> 1) ? g_V : g_U;
    int g = lane >> 2, cc = lane & 3;
#pragma unroll
    for (int mt = 0; mt < 4; mt++)
#pragma unroll
        for (int nt = 0; nt < 4; nt++) {
            int row0 = bm + mt * 16 + g;
            int col = h * 64 + nh * 32 + nt * 8 + cc * 2;
            if (row0 < N)
                *(float2*)(base + (size_t)row0 * HDIM + col) =
                    make_float2(acc[mt][nt][0], acc[mt][nt][1]);
            if (row0 + 8 < N)
                *(float2*)(base + (size_t)(row0 + 8) * HDIM + col) =
                    make_float2(acc[mt][nt][2], acc[mt][nt][3]);
        }
}

// ---------------------------------------------------------------------------
// K3: fused edge kernel — single-pass ONLINE softmax + aggregation,
// 2 edges per iteration (interleaved shuffle-reduce chains for ILP).
// One warp per dst node; lanes 0-15 head0 (4 channels each), 16-31 head1.
// ---------------------------------------------------------------------------
__global__ __launch_bounds__(256) void k_edge_fused(const float* __restrict__ avec,
                                                    const int* __restrict__ src,
                                                    float* __restrict__ out, int N) {
    int t = blockIdx.x * blockDim.x + threadIdx.x;
    int n = t >> 5, lane = t & 31;
    if (n >= N) return;
    int e0 = g_rowptr[n], e1 = g_rowptr[n + 1];
    const float4* U4  = (const float4*)g_U;
    const float4* V4  = (const float4*)g_V;
    const float4* Wh4 = (const float4*)g_Wh;
    float4 a = ((const float4*)avec)[lane];
    float4 acc = make_float4(0.f, 0.f, 0.f, 0.f);
    float ssum = 0.f;

    if (e1 > e0) {
        float4 v = V4[(size_t)n * 32 + lane];
        float m = -1e30f;

        // prefetch first pair
        float4 u0 = make_float4(0.f, 0.f, 0.f, 0.f), w0 = u0, u1 = u0, w1 = u0;
        {
            int s0 = src[e0];
            u0 = U4[(size_t)s0 * 32 + lane];
            w0 = Wh4[(size_t)s0 * 32 + lane];
            if (e0 + 1 < e1) {
                int s1 = src[e0 + 1];
                u1 = U4[(size_t)s1 * 32 + lane];
                w1 = Wh4[(size_t)s1 * 32 + lane];
            }
        }

        for (int e = e0; e < e1; e += 2) {
            bool two = (e + 1 < e1);
            float4 cu0 = u0, cw0 = w0, cu1 = u1, cw1 = w1;
            // prefetch next pair
            if (e + 2 < e1) {
                int s0 = src[e + 2];
                u0 = U4[(size_t)s0 * 32 + lane];
                w0 = Wh4[(size_t)s0 * 32 + lane];
            }
            if (e + 3 < e1) {
                int s1 = src[e + 3];
                u1 = U4[(size_t)s1 * 32 + lane];
                w1 = Wh4[(size_t)s1 * 32 + lane];
            }
            // two logit dots
            float q, z0, z1;
            q = cu0.x + v.x; z0  = fmaxf(q, ALPHA_C * q) * a.x;
            q = cu1.x + v.x; z1  = fmaxf(q, ALPHA_C * q) * a.x;
            q = cu0.y + v.y; z0 += fmaxf(q, ALPHA_C * q) * a.y;
            q = cu1.y + v.y; z1 += fmaxf(q, ALPHA_C * q) * a.y;
            q = cu0.z + v.z; z0 += fmaxf(q, ALPHA_C * q) * a.z;
            q = cu1.z + v.z; z1 += fmaxf(q, ALPHA_C * q) * a.z;
            q = cu0.w + v.w; z0 += fmaxf(q, ALPHA_C * q) * a.w;
            q = cu1.w + v.w; z1 += fmaxf(q, ALPHA_C * q) * a.w;
            // interleaved 16-lane butterfly reduces (2 independent chains)
            z0 += __shfl_xor_sync(0xffffffffu, z0, 8);
            z1 += __shfl_xor_sync(0xffffffffu, z1, 8);
            z0 += __shfl_xor_sync(0xffffffffu, z0, 4);
            z1 += __shfl_xor_sync(0xffffffffu, z1, 4);
            z0 += __shfl_xor_sync(0xffffffffu, z0, 2);
            z1 += __shfl_xor_sync(0xffffffffu, z1, 2);
            z0 += __shfl_xor_sync(0xffffffffu, z0, 1);
            z1 += __shfl_xor_sync(0xffffffffu, z1, 1);
            float l0 = z0 * INV_TEMP;
            float l1 = two ? (z1 * INV_TEMP) : -1e30f;
            // online softmax update
            float mn = fmaxf(m, fmaxf(l0, l1));
            float cs = __expf(m - mn);          // 0 on first iter (m=-1e30)
            float p0 = __expf(l0 - mn);
            float p1 = __expf(l1 - mn);         // 0 when !two
            ssum = ssum * cs + p0 + p1;
            acc.x = acc.x * cs + p0 * cw0.x + p1 * cw1.x;
            acc.y = acc.y * cs + p0 * cw0.y + p1 * cw1.y;
            acc.z = acc.z * cs + p0 * cw0.z + p1 * cw1.z;
            acc.w = acc.w * cs + p0 * cw0.w + p1 * cw1.w;
            m = mn;
        }
        float inv = 1.0f / (ssum + 1e-9f);
        acc.x *= inv; acc.y *= inv; acc.z *= inv; acc.w *= inv;
    }

    // mean over heads: lane l<16 combines with lane l+16 (same channels)
    float bx = __shfl_down_sync(0xffffffffu, acc.x, 16);
    float by = __shfl_down_sync(0xffffffffu, acc.y, 16);
    float bz = __shfl_down_sync(0xffffffffu, acc.z, 16);
    float bw = __shfl_down_sync(0xffffffffu, acc.w, 16);
    if (lane < 16) {
        float4 r = make_float4((acc.x + bx) * 0.5f, (acc.y + by) * 0.5f,
                               (acc.z + bz) * 0.5f, (acc.w + bw) * 0.5f);
        ((float4*)out)[(size_t)n * 16 + lane] = r;
    }
}

// ---------------------------------------------------------------------------
extern "C" void kernel_launch(void* const* d_in, const int* in_sizes, int n_in,
                              void* d_out, int out_size) {
    const float* x     = (const float*)d_in[0];
    const float* W     = (const float*)d_in[1];
    const float* Wattn = (const float*)d_in[2];
    const float* avec  = (const float*)d_in[3];
    const int*   src   = (const int*)d_in[4];
    const int*   dst   = (const int*)d_in[5];
    float* out = (float*)d_out;
    int N = in_sizes[0] / INDIM;
    int E = in_sizes[4];

    k_rowptr<<<(E + 1 + 255) / 256, 256>>>(dst, E, N);
    k_prep_w<<<64, 256>>>(W);
    k_prep_wa<<<32, 256>>>(Wattn);
    k_wh_mma<<<(N + 63) / 64, 256>>>(x, N);
    k_uv_mma<<<(N + 63) / 64, 256>>>(N);
    k_edge_fused<<<(N + 7) / 8, 256>>>(avec, src, out, N);
}

// round 11
// speedup vs baseline: 2.0965x; 1.0382x over previous
#include <cuda_runtime.h>
#include <cuda_bf16.h>
#include <cstdint>

// Problem constants
#define NN 50000
#define EE 400000
#define INDIM 256
#define HDIM 128
#define ALPHA_C 0.2f
#define INV_TEMP (1.0f / 0.55f)
#define ASTRIDE 72            // bf16 elems per smem row (144B: conflict-free ldmatrix)

// Scratch (device globals)
__device__ float g_Wh[NN * HDIM];
__device__ float g_U[NN * HDIM];
__device__ float g_V[NN * HDIM];
__device__ int   g_rowptr[NN + 1];
// B fragments in native mma register layout (bf16x2 words):
// g_WB : [leg2][kt16][nt16][lane32][reg2]   (W  -> 128KB)
__device__ uint32_t g_WB[32768];
// g_WaB: [leg2][q4][kt4][nt8][lane32][reg2] (Wa -> 64KB)
__device__ uint32_t g_WaB[16384];

// ---------------- helpers ----------------
__device__ __forceinline__ uint32_t su32(const void* p) {
    uint32_t a;
    asm("{ .reg .u64 t; cvta.to.shared.u64 t, %1; cvt.u32.u64 %0, t; }" : "=r"(a) : "l"(p));
    return a;
}
__device__ __forceinline__ void split2(float v, unsigned short& hi, unsigned short& lo) {
    __nv_bfloat16 b = __float2bfloat16_rn(v);
    hi = __bfloat16_as_ushort(b);
    lo = __bfloat16_as_ushort(__float2bfloat16_rn(v - __bfloat162float(b)));
}
__device__ __forceinline__ void mma_bf16(float* c, const uint32_t* a, uint32_t b0, uint32_t b1) {
    asm volatile(
        "mma.sync.aligned.m16n8k16.row.col.f32.bf16.bf16.f32 "
        "{%0,%1,%2,%3},{%4,%5,%6,%7},{%8,%9},{%0,%1,%2,%3};"
        : "+f"(c[0]), "+f"(c[1]), "+f"(c[2]), "+f"(c[3])
        : "r"(a[0]), "r"(a[1]), "r"(a[2]), "r"(a[3]), "r"(b0), "r"(b1));
}
__device__ __forceinline__ void ldmA(uint32_t* a, uint32_t addr) {
    asm volatile("ldmatrix.sync.aligned.m8n8.x4.shared.b16 {%0,%1,%2,%3}, [%4];"
        : "=r"(a[0]), "=r"(a[1]), "=r"(a[2]), "=r"(a[3]) : "r"(addr));
}

// ---------------------------------------------------------------------------
// K0: CSR row pointers from sorted dst.
// ---------------------------------------------------------------------------
__global__ void k_rowptr(const int* __restrict__ dst, int E, int N) {
    int e = blockIdx.x * blockDim.x + threadIdx.x;
    if (e > E) return;
    int cur  = (e < E) ? dst[e] : N;
    int prev = (e == 0) ? -1 : dst[e - 1];
    for (int n = prev + 1; n <= cur; n++) g_rowptr[n] = e;
}

// ---------------------------------------------------------------------------
// Prep W -> B fragments. idx = [kt16][nt16][lane32][reg2].
// ---------------------------------------------------------------------------
__global__ void k_prep_w(const float* __restrict__ W) {
    int idx = blockIdx.x * 256 + threadIdx.x;    // 0..16383
    int reg = idx & 1, lane = (idx >> 1) & 31, nt = (idx >> 6) & 15, kt = idx >> 10;
    int cc = lane & 3, g = lane >> 2;
    int k0 = kt * 16 + reg * 8 + cc * 2;
    int n  = nt * 8 + g;
    unsigned short h0, l0, h1, l1;
    split2(W[(size_t)k0 * HDIM + n], h0, l0);
    split2(W[(size_t)(k0 + 1) * HDIM + n], h1, l1);
    g_WB[idx]         = ((uint32_t)h1 << 16) | h0;
    g_WB[16384 + idx] = ((uint32_t)l1 << 16) | l0;
}

// ---------------------------------------------------------------------------
// Prep Wa -> B fragments. idx = [q4][kt4][nt8][lane32][reg2].
// ---------------------------------------------------------------------------
__global__ void k_prep_wa(const float* __restrict__ Wa) {
    int idx = blockIdx.x * 256 + threadIdx.x;    // 0..8191
    int reg = idx & 1, lane = (idx >> 1) & 31, nt = (idx >> 6) & 7;
    int kt = (idx >> 9) & 3, q = idx >> 11;
    int cc = lane & 3, g = lane >> 2;
    int h = q & 1, p = q >> 1;
    int f0 = kt * 16 + reg * 8 + cc * 2;
    int n  = nt * 8 + g;
    unsigned short h0, l0, h1, l1;
    split2(Wa[h * 8192 + (p * 64 + f0) * 64 + n], h0, l0);
    split2(Wa[h * 8192 + (p * 64 + f0 + 1) * 64 + n], h1, l1);
    g_WaB[idx]        = ((uint32_t)h1 << 16) | h0;
    g_WaB[8192 + idx] = ((uint32_t)l1 << 16) | l0;
}

// ---------------------------------------------------------------------------
// K1+K2 fused: per 64-row CTA,
//  Phase 1: Wh = x @ W (mma bf16 3-term), reg-double-buffered x staging.
//  Phase 2: split in-register Wh acc -> smem A[h][leg] (k_uv layout),
//           also write fp32 Wh to gmem for the edge kernel.
//  Phase 3: U/V = Wh_h @ Wa (mma bf16 3-term) from smem.
// Phase-1 staging aliases A[0][0]/A[0][1].
// ---------------------------------------------------------------------------
__global__ __launch_bounds__(256, 2) void k_whuv_mma(const float* __restrict__ x, int N) {
    __shared__ __align__(16) __nv_bfloat16 A[2][2][64 * ASTRIDE];  // [h][leg]
    int tid = threadIdx.x, wid = tid >> 5, lane = tid & 31;
    int bm = blockIdx.x * 64;
    int wm = wid & 1, wn = wid >> 1;          // phase-1 roles: 2m x 4n
    uint32_t ah_b = su32(A[0][0]), al_b = su32(A[0][1]);

    // ---------------- Phase 1: Wh ----------------
    float acc[2][4][4];
#pragma unroll
    for (int mt = 0; mt < 2; mt++)
#pragma unroll
        for (int nt = 0; nt < 4; nt++)
#pragma unroll
            for (int r = 0; r < 4; r++) acc[mt][nt][r] = 0.f;

    int lrow = lane & 15, lch = (lane >> 4) * 8;
    int srow = tid >> 4, skq = (tid & 15) * 4;       // this thread's staging coords

    float4 pre[4];
#pragma unroll
    for (int i = 0; i < 4; i++) {
        int gr = bm + srow + i * 16;
        pre[i] = make_float4(0.f, 0.f, 0.f, 0.f);
        if (gr < N) pre[i] = *(const float4*)(x + (size_t)gr * INDIM + skq);
    }

    for (int kc = 0; kc < 4; kc++) {
        // store prefetched chunk -> smem (split hi/lo)
#pragma unroll
        for (int i = 0; i < 4; i++) {
            int row = srow + i * 16;
            float4 v = pre[i];
            unsigned short hx, lx, hy, ly, hz, lz, hw, lw;
            split2(v.x, hx, lx); split2(v.y, hy, ly);
            split2(v.z, hz, lz); split2(v.w, hw, lw);
            *(uint2*)&A[0][0][row * ASTRIDE + skq] =
                make_uint2(((uint32_t)hy << 16) | hx, ((uint32_t)hw << 16) | hz);
            *(uint2*)&A[0][1][row * ASTRIDE + skq] =
                make_uint2(((uint32_t)ly << 16) | lx, ((uint32_t)lw << 16) | lz);
        }
        __syncthreads();
        // prefetch next chunk (overlaps mma phase below)
        if (kc < 3) {
#pragma unroll
            for (int i = 0; i < 4; i++) {
                int gr = bm + srow + i * 16;
                pre[i] = make_float4(0.f, 0.f, 0.f, 0.f);
                if (gr < N) pre[i] = *(const float4*)(x + (size_t)gr * INDIM + (kc + 1) * 64 + skq);
            }
        }
#pragma unroll
        for (int kk = 0; kk < 4; kk++) {
            uint32_t afh[2][4], afl[2][4];
#pragma unroll
            for (int mt = 0; mt < 2; mt++) {
                uint32_t off = ((wm * 32 + mt * 16 + lrow) * ASTRIDE + kk * 16 + lch) * 2;
                ldmA(afh[mt], ah_b + off);
                ldmA(afl[mt], al_b + off);
            }
            int kt = kc * 4 + kk;
            const uint32_t* Bp = g_WB + (size_t)(kt * 16 + wn * 4) * 64 + lane * 2;
#pragma unroll
            for (int nt = 0; nt < 4; nt++) {
                uint2 bh = *(const uint2*)(Bp + nt * 64);
                uint2 bl = *(const uint2*)(Bp + nt * 64 + 16384);
#pragma unroll
                for (int mt = 0; mt < 2; mt++) {
                    mma_bf16(acc[mt][nt], afh[mt], bh.x, bh.y);
                    mma_bf16(acc[mt][nt], afh[mt], bl.x, bl.y);
                    mma_bf16(acc[mt][nt], afl[mt], bh.x, bh.y);
                }
            }
        }
        __syncthreads();
    }

    // ---------------- Phase 2: epilogue + re-stage Wh (split) ----------------
    {
        int g = lane >> 2, cc = lane & 3;
#pragma unroll
        for (int mt = 0; mt < 2; mt++)
#pragma unroll
            for (int nt = 0; nt < 4; nt++) {
                int lrow0 = wm * 32 + mt * 16 + g;       // local tile row
                int col = wn * 32 + nt * 8 + cc * 2;
                int h = col >> 6, kl = col & 63;
                unsigned short h0, l0, h1, l1, h2, l2, h3, l3;
                split2(acc[mt][nt][0], h0, l0);
                split2(acc[mt][nt][1], h1, l1);
                split2(acc[mt][nt][2], h2, l2);
                split2(acc[mt][nt][3], h3, l3);
                *(uint32_t*)&A[h][0][lrow0 * ASTRIDE + kl] = ((uint32_t)h1 << 16) | h0;
                *(uint32_t*)&A[h][1][lrow0 * ASTRIDE + kl] = ((uint32_t)l1 << 16) | l0;
                *(uint32_t*)&A[h][0][(lrow0 + 8) * ASTRIDE + kl] = ((uint32_t)h3 << 16) | h2;
                *(uint32_t*)&A[h][1][(lrow0 + 8) * ASTRIDE + kl] = ((uint32_t)l3 << 16) | l2;
                int grow0 = bm + lrow0;
                if (grow0 < N)
                    *(float2*)(g_Wh + (size_t)grow0 * HDIM + col) =
                        make_float2(acc[mt][nt][0], acc[mt][nt][1]);
                if (grow0 + 8 < N)
                    *(float2*)(g_Wh + (size_t)(grow0 + 8) * HDIM + col) =
                        make_float2(acc[mt][nt][2], acc[mt][nt][3]);
            }
    }
    __syncthreads();

    // ---------------- Phase 3: U/V ----------------
    {
        int q = wid >> 1, nh = wid & 1, h = q & 1;
        uint32_t uah_b = su32(A[h][0]), ual_b = su32(A[h][1]);
        float uacc[4][4][4];
#pragma unroll
        for (int mt = 0; mt < 4; mt++)
#pragma unroll
            for (int nt = 0; nt < 4; nt++)
#pragma unroll
                for (int r = 0; r < 4; r++) uacc[mt][nt][r] = 0.f;

#pragma unroll
        for (int kk = 0; kk < 4; kk++) {
            uint32_t afh[4][4], afl[4][4];
#pragma unroll
            for (int mt = 0; mt < 4; mt++) {
                uint32_t off = ((mt * 16 + lrow) * ASTRIDE + kk * 16 + lch) * 2;
                ldmA(afh[mt], uah_b + off);
                ldmA(afl[mt], ual_b + off);
            }
            const uint32_t* Bp = g_WaB + (size_t)((q * 4 + kk) * 8 + nh * 4) * 64 + lane * 2;
#pragma unroll
            for (int nt = 0; nt < 4; nt++) {
                uint2 bh = *(const uint2*)(Bp + nt * 64);
                uint2 bl = *(const uint2*)(Bp + nt * 64 + 8192);
#pragma unroll
                for (int mt = 0; mt < 4; mt++) {
                    mma_bf16(uacc[mt][nt], afh[mt], bh.x, bh.y);
                    mma_bf16(uacc[mt][nt], afh[mt], bl.x, bl.y);
                    mma_bf16(uacc[mt][nt], afl[mt], bh.x, bh.y);
                }
            }
        }

        float* base = (q >> 1) ? g_V : g_U;
        int g = lane >> 2, cc = lane & 3;
#pragma unroll
        for (int mt = 0; mt < 4; mt++)
#pragma unroll
            for (int nt = 0; nt < 4; nt++) {
                int row0 = bm + mt * 16 + g;
                int col = h * 64 + nh * 32 + nt * 8 + cc * 2;
                if (row0 < N)
                    *(float2*)(base + (size_t)row0 * HDIM + col) =
                        make_float2(uacc[mt][nt][0], uacc[mt][nt][1]);
                if (row0 + 8 < N)
                    *(float2*)(base + (size_t)(row0 + 8) * HDIM + col) =
                        make_float2(uacc[mt][nt][2], uacc[mt][nt][3]);
            }
    }
}

// ---------------------------------------------------------------------------
// K3: fused edge kernel — single-pass online softmax + aggregation,
// 2 edges per iteration. One warp per dst node. (unchanged)
// ---------------------------------------------------------------------------
__global__ __launch_bounds__(256) void k_edge_fused(const float* __restrict__ avec,
                                                    const int* __restrict__ src,
                                                    float* __restrict__ out, int N) {
    int t = blockIdx.x * blockDim.x + threadIdx.x;
    int n = t >> 5, lane = t & 31;
    if (n >= N) return;
    int e0 = g_rowptr[n], e1 = g_rowptr[n + 1];
    const float4* U4  = (const float4*)g_U;
    const float4* V4  = (const float4*)g_V;
    const float4* Wh4 = (const float4*)g_Wh;
    float4 a = ((const float4*)avec)[lane];
    float4 acc = make_float4(0.f, 0.f, 0.f, 0.f);
    float ssum = 0.f;

    if (e1 > e0) {
        float4 v = V4[(size_t)n * 32 + lane];
        float m = -1e30f;

        float4 u0 = make_float4(0.f, 0.f, 0.f, 0.f), w0 = u0, u1 = u0, w1 = u0;
        {
            int s0 = src[e0];
            u0 = U4[(size_t)s0 * 32 + lane];
            w0 = Wh4[(size_t)s0 * 32 + lane];
            if (e0 + 1 < e1) {
                int s1 = src[e0 + 1];
                u1 = U4[(size_t)s1 * 32 + lane];
                w1 = Wh4[(size_t)s1 * 32 + lane];
            }
        }

        for (int e = e0; e < e1; e += 2) {
            bool two = (e + 1 < e1);
            float4 cu0 = u0, cw0 = w0, cu1 = u1, cw1 = w1;
            if (e + 2 < e1) {
                int s0 = src[e + 2];
                u0 = U4[(size_t)s0 * 32 + lane];
                w0 = Wh4[(size_t)s0 * 32 + lane];
            }
            if (e + 3 < e1) {
                int s1 = src[e + 3];
                u1 = U4[(size_t)s1 * 32 + lane];
                w1 = Wh4[(size_t)s1 * 32 + lane];
            }
            float q, z0, z1;
            q = cu0.x + v.x; z0  = fmaxf(q, ALPHA_C * q) * a.x;
            q = cu1.x + v.x; z1  = fmaxf(q, ALPHA_C * q) * a.x;
            q = cu0.y + v.y; z0 += fmaxf(q, ALPHA_C * q) * a.y;
            q = cu1.y + v.y; z1 += fmaxf(q, ALPHA_C * q) * a.y;
            q = cu0.z + v.z; z0 += fmaxf(q, ALPHA_C * q) * a.z;
            q = cu1.z + v.z; z1 += fmaxf(q, ALPHA_C * q) * a.z;
            q = cu0.w + v.w; z0 += fmaxf(q, ALPHA_C * q) * a.w;
            q = cu1.w + v.w; z1 += fmaxf(q, ALPHA_C * q) * a.w;
            z0 += __shfl_xor_sync(0xffffffffu, z0, 8);
            z1 += __shfl_xor_sync(0xffffffffu, z1, 8);
            z0 += __shfl_xor_sync(0xffffffffu, z0, 4);
            z1 += __shfl_xor_sync(0xffffffffu, z1, 4);
            z0 += __shfl_xor_sync(0xffffffffu, z0, 2);
            z1 += __shfl_xor_sync(0xffffffffu, z1, 2);
            z0 += __shfl_xor_sync(0xffffffffu, z0, 1);
            z1 += __shfl_xor_sync(0xffffffffu, z1, 1);
            float l0 = z0 * INV_TEMP;
            float l1 = two ? (z1 * INV_TEMP) : -1e30f;
            float mn = fmaxf(m, fmaxf(l0, l1));
            float cs = __expf(m - mn);
            float p0 = __expf(l0 - mn);
            float p1 = __expf(l1 - mn);
            ssum = ssum * cs + p0 + p1;
            acc.x = acc.x * cs + p0 * cw0.x + p1 * cw1.x;
            acc.y = acc.y * cs + p0 * cw0.y + p1 * cw1.y;
            acc.z = acc.z * cs + p0 * cw0.z + p1 * cw1.z;
            acc.w = acc.w * cs + p0 * cw0.w + p1 * cw1.w;
            m = mn;
        }
        float inv = 1.0f / (ssum + 1e-9f);
        acc.x *= inv; acc.y *= inv; acc.z *= inv; acc.w *= inv;
    }

    float bx = __shfl_down_sync(0xffffffffu, acc.x, 16);
    float by = __shfl_down_sync(0xffffffffu, acc.y, 16);
    float bz = __shfl_down_sync(0xffffffffu, acc.z, 16);
    float bw = __shfl_down_sync(0xffffffffu, acc.w, 16);
    if (lane < 16) {
        float4 r = make_float4((acc.x + bx) * 0.5f, (acc.y + by) * 0.5f,
                               (acc.z + bz) * 0.5f, (acc.w + bw) * 0.5f);
        ((float4*)out)[(size_t)n * 16 + lane] = r;
    }
}

// ---------------------------------------------------------------------------
extern "C" void kernel_launch(void* const* d_in, const int* in_sizes, int n_in,
                              void* d_out, int out_size) {
    const float* x     = (const float*)d_in[0];
    const float* W     = (const float*)d_in[1];
    const float* Wattn = (const float*)d_in[2];
    const float* avec  = (const float*)d_in[3];
    const int*   src   = (const int*)d_in[4];
    const int*   dst   = (const int*)d_in[5];
    float* out = (float*)d_out;
    int N = in_sizes[0] / INDIM;
    int E = in_sizes[4];

    k_rowptr<<<(E + 1 + 255) / 256, 256>>>(dst, E, N);
    k_prep_w<<<64, 256>>>(W);
    k_prep_wa<<<32, 256>>>(Wattn);
    k_whuv_mma<<<(N + 63) / 64, 256>>>(x, N);
    k_edge_fused<<<(N + 7) / 8, 256>>>(avec, src, out, N);
}